// round 4
// baseline (speedup 1.0000x reference)
#include <cuda_runtime.h>
#include <math.h>

#define BB   128
#define TT   256
#define HH   1024
#define KG   256     /* HH/4 feature-groups */
#define NBLK 128
#define NJ   8       /* output cols per CTA */
#define NTH  1024
#define WST  257     /* weight col stride in float4 (bank-conflict-free) */
#define CH   8       /* k4 per staged chunk */
#define NCH  32      /* chunks per phase */

typedef unsigned long long u64;

/* Scratch (static device globals; no runtime allocation). */
__device__ float4 g_pre0[(size_t)TT * KG * BB];   /* [t][j4][b] */
__device__ float4 g_h0buf[2][KG * BB];            /* layer-0 hidden, double buffered, [k4][b] */
__device__ float4 g_h1buf[2][KG * BB];            /* layer-1 hidden */
__device__ unsigned int g_cnt;                    /* grid barrier counter */

/* ---------------- packed fp32x2 helpers ---------------- */
__device__ __forceinline__ u64 fma2(u64 a, u64 b, u64 c) {
    u64 d; asm("fma.rn.f32x2 %0, %1, %2, %3;" : "=l"(d) : "l"(a), "l"(b), "l"(c)); return d;
}
__device__ __forceinline__ u64 pack2(float x, float y) {
    u64 r; asm("mov.b64 %0, {%1, %2};" : "=l"(r) : "f"(x), "f"(y)); return r;
}
__device__ __forceinline__ float2 unpk(u64 v) {
    float2 f; asm("mov.b64 {%0, %1}, %2;" : "=f"(f.x), "=f"(f.y) : "l"(v)); return f;
}
__device__ __forceinline__ void cp16(unsigned int saddr, const void* g) {
    asm volatile("cp.async.cg.shared.global [%0], [%1], 16;" :: "r"(saddr), "l"(g));
}
__device__ __forceinline__ void cp_commit() {
    asm volatile("cp.async.commit_group;");
}
template <int N> __device__ __forceinline__ void cp_wait() {
    asm volatile("cp.async.wait_group %0;" :: "n"(N));
}

/* ------------------------------------------------------------------ */
/* Kernel 1: pre0[t][j][b] = sum_k x[b][t][k]*Wi0[k][j] + bi0[j]       */
/* ------------------------------------------------------------------ */
__global__ __launch_bounds__(256) void pre_gemm(const float* __restrict__ x,
                                                const float* __restrict__ Wi,
                                                const float* __restrict__ bi)
{
    if (blockIdx.x == 0 && blockIdx.y == 0 && threadIdx.x == 0) g_cnt = 0u;

    __shared__ float  sA[32][129];
    __shared__ float4 sB[32 * 16];

    const int t     = blockIdx.y;
    const int jbase = blockIdx.x * 64;
    const int tid   = threadIdx.x;
    const int rid   = tid & 31;
    const int cid   = tid >> 5;

    u64 acc[4][4];
#pragma unroll
    for (int i = 0; i < 4; ++i)
#pragma unroll
        for (int j = 0; j < 4; ++j) acc[i][j] = 0ull;

    const int brow = tid >> 1;
    const int half = tid & 1;

    for (int k0 = 0; k0 < HH; k0 += 32) {
        __syncthreads();
        const float* xs = x + ((size_t)brow * TT + t) * HH + k0 + half * 16;
#pragma unroll
        for (int q = 0; q < 4; ++q) {
            float4 v = *(const float4*)(xs + 4 * q);
            int kk = half * 16 + 4 * q;
            sA[kk + 0][brow] = v.x; sA[kk + 1][brow] = v.y;
            sA[kk + 2][brow] = v.z; sA[kk + 3][brow] = v.w;
        }
#pragma unroll
        for (int q = 0; q < 2; ++q) {
            int idx = tid + 256 * q;
            int kk = idx >> 4, jf = idx & 15;
            sB[idx] = *(const float4*)(Wi + (size_t)(k0 + kk) * HH + jbase + 4 * jf);
        }
        __syncthreads();

#pragma unroll
        for (int kk = 0; kk < 32; ++kk) {
            float a0 = sA[kk][rid], a1 = sA[kk][rid + 32];
            float a2 = sA[kk][rid + 64], a3 = sA[kk][rid + 96];
            const ulonglong2* bp = (const ulonglong2*)&sB[kk * 16 + cid * 2];
            ulonglong2 bb0 = bp[0];
            ulonglong2 bb1 = bp[1];
            u64 ad0 = pack2(a0, a0), ad1 = pack2(a1, a1);
            u64 ad2 = pack2(a2, a2), ad3 = pack2(a3, a3);
            acc[0][0] = fma2(ad0, bb0.x, acc[0][0]); acc[0][1] = fma2(ad0, bb0.y, acc[0][1]);
            acc[0][2] = fma2(ad0, bb1.x, acc[0][2]); acc[0][3] = fma2(ad0, bb1.y, acc[0][3]);
            acc[1][0] = fma2(ad1, bb0.x, acc[1][0]); acc[1][1] = fma2(ad1, bb0.y, acc[1][1]);
            acc[1][2] = fma2(ad1, bb1.x, acc[1][2]); acc[1][3] = fma2(ad1, bb1.y, acc[1][3]);
            acc[2][0] = fma2(ad2, bb0.x, acc[2][0]); acc[2][1] = fma2(ad2, bb0.y, acc[2][1]);
            acc[2][2] = fma2(ad2, bb1.x, acc[2][2]); acc[2][3] = fma2(ad2, bb1.y, acc[2][3]);
            acc[3][0] = fma2(ad3, bb0.x, acc[3][0]); acc[3][1] = fma2(ad3, bb0.y, acc[3][1]);
            acc[3][2] = fma2(ad3, bb1.x, acc[3][2]); acc[3][3] = fma2(ad3, bb1.y, acc[3][3]);
        }
    }

    float biv[8];
#pragma unroll
    for (int j = 0; j < 8; ++j) biv[j] = __ldg(&bi[jbase + cid * 8 + j]);

    const int jg = (jbase + cid * 8) >> 2;
#pragma unroll
    for (int i = 0; i < 4; ++i) {
        int row = rid + 32 * i;
#pragma unroll
        for (int gq = 0; gq < 2; ++gq) {
            float2 u0 = unpk(acc[i][2 * gq]);
            float2 u1 = unpk(acc[i][2 * gq + 1]);
            float4 v;
            v.x = u0.x + biv[4 * gq + 0];
            v.y = u0.y + biv[4 * gq + 1];
            v.z = u1.x + biv[4 * gq + 2];
            v.w = u1.y + biv[4 * gq + 3];
            g_pre0[((size_t)t * KG + jg + gq) * BB + row] = v;
        }
    }
}

/* ------------------------------------------------------------------ */
__device__ __forceinline__ void grid_sync(unsigned int target)
{
    __syncthreads();
    if (threadIdx.x == 0) {
        __threadfence();
        atomicAdd(&g_cnt, 1u);
        while (*(volatile unsigned int*)&g_cnt < target) { }
        __threadfence();
    }
    __syncthreads();
}

/* SMEM float4 offsets */
#define OFF_WI1  0
#define OFF_WH1  (8 * WST)
#define OFF_WH0  (16 * WST)
#define OFF_A    (24 * WST)          /* 3 bufs x 2 mats x 1024 f4 */
#define ABUF(b, m) (OFF_A + ((b) * 2 + (m)) * (CH * BB))
#define SMEM_F4  (24 * WST + 6 * CH * BB)

/* ------------------------------------------------------------------ */
/* Kernel 2: persistent RNN. thread = (row 0..127, col 0..7), full K.  */
/* A0/A1 staged via cp.async (3 bufs, depth-2). No K reduction.        */
/* ------------------------------------------------------------------ */
__global__ __launch_bounds__(NTH, 1) void rnn_persist(const float* __restrict__ h0,
                                                      const float* __restrict__ Wi,
                                                      const float* __restrict__ bi,
                                                      const float* __restrict__ Wh,
                                                      const float* __restrict__ bh,
                                                      float* __restrict__ out)
{
    extern __shared__ float4 smem4[];
    unsigned int smem_base = (unsigned int)__cvta_generic_to_shared(smem4);

    const int cta = blockIdx.x;
    const int th  = threadIdx.x;
    const int row = th >> 3;           /* 0..127 */
    const int col = th & 7;            /* 0..7   */
    const int j0  = cta * NJ;
    const int jg4 = (j0 + col) >> 2;
    const int cl  = col & 3;

    /* stage mapping */
    const int sk4 = th >> 7;           /* 0..7  */
    const int sr  = th & 127;          /* 0..127 */

    const float* Wi1g = Wi + (size_t)HH * HH;
    const float* Wh1g = Wh + (size_t)HH * HH;

    /* One-time: gather weight column slices into SMEM ([col][WST] f4 over k). */
    for (int idx = th; idx < 2048; idx += NTH) {
        int jl = idx >> 8, k4 = idx & 255;
        int j = j0 + jl;
        int kb = k4 * 4;
        smem4[OFF_WH0 + jl * WST + k4] =
            make_float4(Wh[(size_t)(kb + 0) * HH + j], Wh[(size_t)(kb + 1) * HH + j],
                        Wh[(size_t)(kb + 2) * HH + j], Wh[(size_t)(kb + 3) * HH + j]);
        smem4[OFF_WI1 + jl * WST + k4] =
            make_float4(Wi1g[(size_t)(kb + 0) * HH + j], Wi1g[(size_t)(kb + 1) * HH + j],
                        Wi1g[(size_t)(kb + 2) * HH + j], Wi1g[(size_t)(kb + 3) * HH + j]);
        smem4[OFF_WH1 + jl * WST + k4] =
            make_float4(Wh1g[(size_t)(kb + 0) * HH + j], Wh1g[(size_t)(kb + 1) * HH + j],
                        Wh1g[(size_t)(kb + 2) * HH + j], Wh1g[(size_t)(kb + 3) * HH + j]);
    }

    const float bs1 = __ldg(&bi[HH + j0 + col]) + __ldg(&bh[HH + j0 + col]);
    const float b0r = __ldg(&bh[j0 + col]);

    /* h1 init: CTA covers k4 in [2*cta, 2*cta+2). */
    if (th < 2 * BB) {
        int k4l = th >> 7, b = th & 127;
        g_h1buf[1][(2 * cta + k4l) * BB + b] = *(const float4*)(h0 + HH + 4 * (2 * cta + k4l));
    }
    __syncthreads();

    /* hn0[0] init: full-K dot per (col) [redundant across rows; one-time]. */
    {
        u64 d = 0ull;
        for (int k4 = 0; k4 < KG; ++k4) {
            ulonglong2 a = *(const ulonglong2*)(h0 + 4 * k4);
            ulonglong2 w = *(const ulonglong2*)&smem4[OFF_WH0 + col * WST + k4];
            d = fma2(a.x, w.x, fma2(a.y, w.y, d));
        }
        float2 f = unpk(d);
        float pre = ((const float*)g_pre0)[((size_t)jg4 * BB + row) * 4 + cl];
        ((float*)g_h0buf[0])[((size_t)jg4 * BB + row) * 4 + cl] = tanhf(pre + f.x + f.y + b0r);
    }

    unsigned int ph = 1;
    grid_sync(ph * NBLK); ++ph;

    for (int t = 0; t < TT; ++t) {
        const float4* A0g = g_h0buf[t & 1];
        const float4* A1g = g_h1buf[(t + 1) & 1];

        /* Prefetch next-step pre0 early (L2 latency hidden under the phase). */
        float preNext = 0.0f;
        if (t < TT - 1)
            preNext = __ldcg(&((const float*)g_pre0)[((size_t)((size_t)(t + 1) * KG + jg4) * BB + row) * 4 + cl]);

        /* Prologue: stage chunks 0,1. */
#pragma unroll
        for (int c = 0; c < 2; ++c) {
            cp16(smem_base + (ABUF(c, 0) + sk4 * BB + sr) * 16, A0g + (c * CH + sk4) * BB + sr);
            cp16(smem_base + (ABUF(c, 1) + sk4 * BB + sr) * 16, A1g + (c * CH + sk4) * BB + sr);
            cp_commit();
        }

        u64 acc1a = 0ull, acc1b = 0ull, acc0 = 0ull;

        for (int c = 0; c < NCH; ++c) {
            if (c < NCH - 1) cp_wait<1>(); else cp_wait<0>();
            __syncthreads();   /* chunk c visible; all threads done with buf (c-1)%3 */

            if (c + 2 < NCH) {
                int b = (c + 2) % 3;
                cp16(smem_base + (ABUF(b, 0) + sk4 * BB + sr) * 16, A0g + ((c + 2) * CH + sk4) * BB + sr);
                cp16(smem_base + (ABUF(b, 1) + sk4 * BB + sr) * 16, A1g + ((c + 2) * CH + sk4) * BB + sr);
                cp_commit();
            }

            const int ab = c % 3;
            const float4* a0p = smem4 + ABUF(ab, 0) + row;
            const float4* a1p = smem4 + ABUF(ab, 1) + row;
            const float4* wp  = smem4 + col * WST + c * CH;
#pragma unroll
            for (int kk = 0; kk < CH; ++kk) {
                ulonglong2 a0 = *(const ulonglong2*)(a0p + kk * BB);
                ulonglong2 a1 = *(const ulonglong2*)(a1p + kk * BB);
                ulonglong2 wi1 = *(const ulonglong2*)(wp + OFF_WI1 + kk);
                acc1a = fma2(a0.x, wi1.x, fma2(a0.y, wi1.y, acc1a));
                ulonglong2 wh1 = *(const ulonglong2*)(wp + OFF_WH1 + kk);
                acc1b = fma2(a1.x, wh1.x, fma2(a1.y, wh1.y, acc1b));
                ulonglong2 wh0 = *(const ulonglong2*)(wp + OFF_WH0 + kk);
                acc0  = fma2(a0.x, wh0.x, fma2(a0.y, wh0.y, acc0));
            }
        }

        /* Tail: no K reduction — this thread owns the full dot. */
        {
            float2 f1a = unpk(acc1a), f1b = unpk(acc1b);
            float y = tanhf(f1a.x + f1a.y + f1b.x + f1b.y + bs1);
            out[((size_t)row * TT + t) * HH + j0 + col] = y;
            ((float*)g_h1buf[t & 1])[((size_t)jg4 * BB + row) * 4 + cl] = y;

            if (t < TT - 1) {
                float2 f0 = unpk(acc0);
                ((float*)g_h0buf[(t + 1) & 1])[((size_t)jg4 * BB + row) * 4 + cl] =
                    tanhf(f0.x + f0.y + preNext + b0r);
            } else {
                float* hn = out + (size_t)BB * TT * HH;
                hn[(size_t)(row * 2 + 1) * HH + j0 + col] = y;
                float l0 = __ldcg(&((const float*)g_h0buf[t & 1])[((size_t)jg4 * BB + row) * 4 + cl]);
                hn[(size_t)(row * 2) * HH + j0 + col] = l0;
            }
        }

        if (t < TT - 1) { grid_sync(ph * NBLK); ++ph; }
    }
}

/* ------------------------------------------------------------------ */
extern "C" void kernel_launch(void* const* d_in, const int* in_sizes, int n_in,
                              void* d_out, int out_size)
{
    const float* x  = (const float*)d_in[0];
    const float* h0 = (const float*)d_in[1];
    const float* Wi = (const float*)d_in[2];
    const float* bi = (const float*)d_in[3];
    const float* Wh = (const float*)d_in[4];
    const float* bh = (const float*)d_in[5];
    float* out = (float*)d_out;

    dim3 g2(16, 256);
    pre_gemm<<<g2, 256>>>(x, Wi, bi);

    size_t smem = (size_t)SMEM_F4 * sizeof(float4);   /* ~192.5 KB */
    cudaFuncSetAttribute(rnn_persist, cudaFuncAttributeMaxDynamicSharedMemorySize, (int)smem);
    rnn_persist<<<NBLK, NTH, smem>>>(h0, Wi, bi, Wh, bh, out);
}

// round 5
// speedup vs baseline: 2.6012x; 2.6012x over previous
#include <cuda_runtime.h>
#include <math.h>

#define BB   128
#define TT   256
#define HH   1024
#define KG   256     /* HH/4 feature-groups */
#define NBLK 128
#define NJ   8       /* output cols per CTA */
#define NTH  512
#define K4G  32      /* k4 steps per K-group (8 groups of 64 slots) */

typedef unsigned long long u64;

/* Scratch (static device globals; no runtime allocation). */
__device__ float4 g_pre0[(size_t)TT * KG * BB];   /* [t][j4][b] */
__device__ float4 g_h0buf[2][KG * BB];            /* layer-0 hidden, double buffered, [k4][b] */
__device__ float4 g_h1buf[2][KG * BB];            /* layer-1 hidden */
__device__ unsigned int g_cnt;                    /* grid barrier counter */

/* ---------------- packed fp32x2 helpers (FFMA2 path) ---------------- */
__device__ __forceinline__ u64 fma2(u64 a, u64 b, u64 c) {
    u64 d; asm("fma.rn.f32x2 %0, %1, %2, %3;" : "=l"(d) : "l"(a), "l"(b), "l"(c)); return d;
}
__device__ __forceinline__ u64 pack2(float x, float y) {
    u64 r; asm("mov.b64 %0, {%1, %2};" : "=l"(r) : "f"(x), "f"(y)); return r;
}
__device__ __forceinline__ float2 unpk(u64 v) {
    float2 f; asm("mov.b64 {%0, %1}, %2;" : "=f"(f.x), "=f"(f.y) : "l"(v)); return f;
}
__device__ __forceinline__ void ldcg2(const float4* p, u64& x, u64& y) {
    asm("ld.global.cg.v2.u64 {%0,%1}, [%2];" : "=l"(x), "=l"(y) : "l"(p));
}

/* ------------------------------------------------------------------ */
/* Kernel 1: pre0[t][j][b] = sum_k x[b][t][k]*Wi0[k][j] + bi0[j]       */
/* ------------------------------------------------------------------ */
__global__ __launch_bounds__(256) void pre_gemm(const float* __restrict__ x,
                                                const float* __restrict__ Wi,
                                                const float* __restrict__ bi)
{
    if (blockIdx.x == 0 && blockIdx.y == 0 && threadIdx.x == 0) g_cnt = 0u;

    __shared__ float  sA[32][129];
    __shared__ float4 sB[32 * 16];

    const int t     = blockIdx.y;
    const int jbase = blockIdx.x * 64;
    const int tid   = threadIdx.x;
    const int rid   = tid & 31;
    const int cid   = tid >> 5;

    u64 acc[4][4];
#pragma unroll
    for (int i = 0; i < 4; ++i)
#pragma unroll
        for (int j = 0; j < 4; ++j) acc[i][j] = 0ull;

    const int brow = tid >> 1;
    const int half = tid & 1;

    for (int k0 = 0; k0 < HH; k0 += 32) {
        __syncthreads();
        const float* xs = x + ((size_t)brow * TT + t) * HH + k0 + half * 16;
#pragma unroll
        for (int q = 0; q < 4; ++q) {
            float4 v = *(const float4*)(xs + 4 * q);
            int kk = half * 16 + 4 * q;
            sA[kk + 0][brow] = v.x; sA[kk + 1][brow] = v.y;
            sA[kk + 2][brow] = v.z; sA[kk + 3][brow] = v.w;
        }
#pragma unroll
        for (int q = 0; q < 2; ++q) {
            int idx = tid + 256 * q;
            int kk = idx >> 4, jf = idx & 15;
            sB[idx] = *(const float4*)(Wi + (size_t)(k0 + kk) * HH + jbase + 4 * jf);
        }
        __syncthreads();

#pragma unroll
        for (int kk = 0; kk < 32; ++kk) {
            float a0 = sA[kk][rid], a1 = sA[kk][rid + 32];
            float a2 = sA[kk][rid + 64], a3 = sA[kk][rid + 96];
            const ulonglong2* bp = (const ulonglong2*)&sB[kk * 16 + cid * 2];
            ulonglong2 bb0 = bp[0];
            ulonglong2 bb1 = bp[1];
            u64 ad0 = pack2(a0, a0), ad1 = pack2(a1, a1);
            u64 ad2 = pack2(a2, a2), ad3 = pack2(a3, a3);
            acc[0][0] = fma2(ad0, bb0.x, acc[0][0]); acc[0][1] = fma2(ad0, bb0.y, acc[0][1]);
            acc[0][2] = fma2(ad0, bb1.x, acc[0][2]); acc[0][3] = fma2(ad0, bb1.y, acc[0][3]);
            acc[1][0] = fma2(ad1, bb0.x, acc[1][0]); acc[1][1] = fma2(ad1, bb0.y, acc[1][1]);
            acc[1][2] = fma2(ad1, bb1.x, acc[1][2]); acc[1][3] = fma2(ad1, bb1.y, acc[1][3]);
            acc[2][0] = fma2(ad2, bb0.x, acc[2][0]); acc[2][1] = fma2(ad2, bb0.y, acc[2][1]);
            acc[2][2] = fma2(ad2, bb1.x, acc[2][2]); acc[2][3] = fma2(ad2, bb1.y, acc[2][3]);
            acc[3][0] = fma2(ad3, bb0.x, acc[3][0]); acc[3][1] = fma2(ad3, bb0.y, acc[3][1]);
            acc[3][2] = fma2(ad3, bb1.x, acc[3][2]); acc[3][3] = fma2(ad3, bb1.y, acc[3][3]);
        }
    }

    float biv[8];
#pragma unroll
    for (int j = 0; j < 8; ++j) biv[j] = __ldg(&bi[jbase + cid * 8 + j]);

    const int jg = (jbase + cid * 8) >> 2;
#pragma unroll
    for (int i = 0; i < 4; ++i) {
        int row = rid + 32 * i;
#pragma unroll
        for (int gq = 0; gq < 2; ++gq) {
            float2 u0 = unpk(acc[i][2 * gq]);
            float2 u1 = unpk(acc[i][2 * gq + 1]);
            float4 v;
            v.x = u0.x + biv[4 * gq + 0];
            v.y = u0.y + biv[4 * gq + 1];
            v.z = u1.x + biv[4 * gq + 2];
            v.w = u1.y + biv[4 * gq + 3];
            g_pre0[((size_t)t * KG + jg + gq) * BB + row] = v;
        }
    }
}

/* ------------------------------------------------------------------ */
__device__ __forceinline__ void grid_sync(unsigned int target)
{
    __syncthreads();
    if (threadIdx.x == 0) {
        __threadfence();
        atomicAdd(&g_cnt, 1u);
        while (*(volatile unsigned int*)&g_cnt < target) { }
        __threadfence();
    }
    __syncthreads();
}

#define RIDX(i, g, s) ((((i) * 8 + (g)) * 65) + (s))

/* jj-body macros (loop1 feeds acc1 via Wi1 + acc0 via Wh0; loop2 feeds acc1 via Wh1) */
#define JJ1(cax, cay, cbx, cby, OFF)                                              \
    {                                                                             \
        int off_ = (OFF);                                                         \
        _Pragma("unroll")                                                         \
        for (int jj = 0; jj < NJ; ++jj) {                                         \
            ulonglong2 w1 = *(const ulonglong2*)&sWi1[jj * 256 + off_];           \
            acc1r0[jj] = fma2(cax, w1.x, fma2(cay, w1.y, acc1r0[jj]));            \
            acc1r1[jj] = fma2(cbx, w1.x, fma2(cby, w1.y, acc1r1[jj]));            \
            ulonglong2 w0 = *(const ulonglong2*)&sWh0[jj * 256 + off_];           \
            acc0r0[jj] = fma2(cax, w0.x, fma2(cay, w0.y, acc0r0[jj]));            \
            acc0r1[jj] = fma2(cbx, w0.x, fma2(cby, w0.y, acc0r1[jj]));            \
        }                                                                         \
    }

#define JJ2(cax, cay, cbx, cby, OFF)                                              \
    {                                                                             \
        int off_ = (OFF);                                                         \
        _Pragma("unroll")                                                         \
        for (int jj = 0; jj < NJ; ++jj) {                                         \
            ulonglong2 w = *(const ulonglong2*)&sWh1[jj * 256 + off_];            \
            acc1r0[jj] = fma2(cax, w.x, fma2(cay, w.y, acc1r0[jj]));              \
            acc1r1[jj] = fma2(cbx, w.x, fma2(cby, w.y, acc1r1[jj]));              \
        }                                                                         \
    }

/* ------------------------------------------------------------------ */
/* Kernel 2: persistent weight-stationary RNN, FFMA2, 512 threads.     */
/* thread = (K-group g of 8, row-slot of 64); rows slot and slot+64.   */
/* Depth-2 prefetch on A-loads; pre0[t+1] hoisted to phase start.      */
/* ------------------------------------------------------------------ */
__global__ __launch_bounds__(NTH, 1) void rnn_persist(const float* __restrict__ h0,
                                                      const float* __restrict__ Wi,
                                                      const float* __restrict__ bi,
                                                      const float* __restrict__ Wh,
                                                      const float* __restrict__ bh,
                                                      float* __restrict__ out)
{
    extern __shared__ float4 smem4[];
    float4* sWh0 = smem4;              /* [8][256] col-slices */
    float4* sWi1 = smem4 + 2048;
    float4* sWh1 = smem4 + 4096;
    float*  sred = (float*)(smem4 + 6144);          /* [32][8][65] partials */
    float*  sdot = sred + 32 * 8 * 65;              /* [8][8] init dot */

    const int cta  = blockIdx.x;
    const int th   = threadIdx.x;
    const int g    = th >> 6;          /* K group 0..7 */
    const int slot = th & 63;          /* row slot: rows slot, slot+64 */
    const int j0   = cta * NJ;

    /* final-pass mapping (all 512 threads): */
    const int frow = th >> 2;          /* 0..127 */
    const int c0   = (th & 3) * 2;     /* cols c0, c0+1 of this CTA's 8 */
    const int fslot = frow & 63;
    const int frh   = frow >> 6;
    const int fjg4  = (j0 + c0) >> 2;  /* both cols in same float4 group */
    const int fcl   = c0 & 3;

    const float* Wi1g = Wi + (size_t)HH * HH;
    const float* Wh1g = Wh + (size_t)HH * HH;

    /* One-time: gather weight column slices into SMEM (float4 over k). */
    for (int idx = th; idx < 2048; idx += NTH) {
        int jl = idx >> 8, k4 = idx & 255;
        int j = j0 + jl;
        int kb = k4 * 4;
        sWh0[idx] = make_float4(Wh[(size_t)(kb + 0) * HH + j], Wh[(size_t)(kb + 1) * HH + j],
                                Wh[(size_t)(kb + 2) * HH + j], Wh[(size_t)(kb + 3) * HH + j]);
        sWi1[idx] = make_float4(Wi1g[(size_t)(kb + 0) * HH + j], Wi1g[(size_t)(kb + 1) * HH + j],
                                Wi1g[(size_t)(kb + 2) * HH + j], Wi1g[(size_t)(kb + 3) * HH + j]);
        sWh1[idx] = make_float4(Wh1g[(size_t)(kb + 0) * HH + j], Wh1g[(size_t)(kb + 1) * HH + j],
                                Wh1g[(size_t)(kb + 2) * HH + j], Wh1g[(size_t)(kb + 3) * HH + j]);
    }

    float bs1[2], b0r[2];
#pragma unroll
    for (int e = 0; e < 2; ++e) {
        bs1[e] = __ldg(&bi[HH + j0 + c0 + e]) + __ldg(&bh[HH + j0 + c0 + e]);
        b0r[e] = __ldg(&bh[j0 + c0 + e]);
    }

    /* h1 init: CTA covers k4 in [2*cta, 2*cta+2), broadcast h0 layer 1. */
    for (int idx = th; idx < 2 * BB; idx += NTH) {
        int k4l = idx >> 7, b = idx & 127;
        g_h1buf[1][(2 * cta + k4l) * BB + b] = *(const float4*)(h0 + HH + 4 * (2 * cta + k4l));
    }
    __syncthreads();

    /* hn0[0] init: dot0[col] = h0_l0 @ Wh0 (shared over batch rows). */
    {
        u64 d[NJ];
#pragma unroll
        for (int jj = 0; jj < NJ; ++jj) d[jj] = 0ull;
        for (int kk = 0; kk < K4G; ++kk) {
            int off = g * K4G + kk;
            ulonglong2 a = *(const ulonglong2*)(h0 + 4 * off);
#pragma unroll
            for (int jj = 0; jj < NJ; ++jj) {
                ulonglong2 w = *(const ulonglong2*)&sWh0[jj * 256 + off];
                d[jj] = fma2(a.x, w.x, fma2(a.y, w.y, d[jj]));
            }
        }
        if (slot == 0) {
#pragma unroll
            for (int jj = 0; jj < NJ; ++jj) {
                float2 f = unpk(d[jj]);
                sdot[g * 8 + jj] = f.x + f.y;
            }
        }
        __syncthreads();
        const float* preF = (const float*)g_pre0;
#pragma unroll
        for (int e = 0; e < 2; ++e) {
            int col = c0 + e;
            float dv = 0.0f;
#pragma unroll
            for (int g2 = 0; g2 < 8; ++g2) dv += sdot[g2 * 8 + col];
            int jg4 = (j0 + col) >> 2;
            float pre = preF[((size_t)jg4 * BB + frow) * 4 + (col & 3)];
            ((float*)g_h0buf[0])[((size_t)jg4 * BB + frow) * 4 + (col & 3)] = tanhf(pre + dv + b0r[e]);
        }
    }

    unsigned int ph = 1;
    grid_sync(ph * NBLK); ++ph;

    for (int t = 0; t < TT; ++t) {
        const float4* A0 = g_h0buf[t & 1];
        const float4* A1 = g_h1buf[(t + 1) & 1];
        const float4* p0 = A0 + (size_t)g * K4G * BB + slot;
        const float4* p1 = A1 + (size_t)g * K4G * BB + slot;

        /* Hoisted prefetch: next-step pre0 (cols c0, c0+1 are adjacent). */
        float2 pn = make_float2(0.0f, 0.0f);
        if (t < TT - 1) {
            const float* pp = (const float*)g_pre0 +
                ((size_t)((size_t)(t + 1) * KG + fjg4) * BB + frow) * 4 + fcl;
            asm("ld.global.cg.v2.f32 {%0,%1}, [%2];" : "=f"(pn.x), "=f"(pn.y) : "l"(pp));
        }

        u64 acc1r0[NJ], acc1r1[NJ], acc0r0[NJ], acc0r1[NJ];
#pragma unroll
        for (int jj = 0; jj < NJ; ++jj) {
            acc1r0[jj] = 0ull; acc1r1[jj] = 0ull;
            acc0r0[jj] = 0ull; acc0r1[jj] = 0ull;
        }

        /* Loop 1: A0 feeds Wi1 (acc1) and Wh0 (acc0). Depth-2 prefetch. */
        {
            u64 A0x, A0y, B0x, B0y, A1x, A1y, B1x, B1y;
            ldcg2(p0,          A0x, A0y); ldcg2(p0 + 64,      B0x, B0y);
            ldcg2(p0 + BB,     A1x, A1y); ldcg2(p0 + BB + 64, B1x, B1y);
#pragma unroll 1
            for (int kk = 0; kk < K4G; kk += 2) {
                int off = g * K4G + kk;
                JJ1(A0x, A0y, B0x, B0y, off);
                if (kk + 2 < K4G) {
                    ldcg2(p0 + (kk + 2) * BB,      A0x, A0y);
                    ldcg2(p0 + (kk + 2) * BB + 64, B0x, B0y);
                }
                JJ1(A1x, A1y, B1x, B1y, off + 1);
                if (kk + 3 < K4G) {
                    ldcg2(p0 + (kk + 3) * BB,      A1x, A1y);
                    ldcg2(p0 + (kk + 3) * BB + 64, B1x, B1y);
                }
            }
        }
        /* Loop 2: A1 feeds Wh1 (acc1). Depth-2 prefetch. */
        {
            u64 A0x, A0y, B0x, B0y, A1x, A1y, B1x, B1y;
            ldcg2(p1,          A0x, A0y); ldcg2(p1 + 64,      B0x, B0y);
            ldcg2(p1 + BB,     A1x, A1y); ldcg2(p1 + BB + 64, B1x, B1y);
#pragma unroll 1
            for (int kk = 0; kk < K4G; kk += 2) {
                int off = g * K4G + kk;
                JJ2(A0x, A0y, B0x, B0y, off);
                if (kk + 2 < K4G) {
                    ldcg2(p1 + (kk + 2) * BB,      A0x, A0y);
                    ldcg2(p1 + (kk + 2) * BB + 64, B0x, B0y);
                }
                JJ2(A1x, A1y, B1x, B1y, off + 1);
                if (kk + 3 < K4G) {
                    ldcg2(p1 + (kk + 3) * BB,      A1x, A1y);
                    ldcg2(p1 + (kk + 3) * BB + 64, B1x, B1y);
                }
            }
        }

        /* Collapse (lo+hi) and write partials for 8-way K reduction. */
#pragma unroll
        for (int jj = 0; jj < NJ; ++jj) {
            float2 v;
            v = unpk(acc1r0[jj]); sred[RIDX(jj,      g, slot)] = v.x + v.y;
            v = unpk(acc1r1[jj]); sred[RIDX(jj + 8,  g, slot)] = v.x + v.y;
            v = unpk(acc0r0[jj]); sred[RIDX(jj + 16, g, slot)] = v.x + v.y;
            v = unpk(acc0r1[jj]); sred[RIDX(jj + 24, g, slot)] = v.x + v.y;
        }
        __syncthreads();

        /* Final pass: all 512 threads, 2 (row,col) scalars each. */
        {
            float* h1w = (float*)g_h1buf[t & 1];
#pragma unroll
            for (int e = 0; e < 2; ++e) {
                int col = c0 + e;
                float s1 = 0.0f;
#pragma unroll
                for (int g2 = 0; g2 < 8; ++g2) s1 += sred[RIDX(col + 8 * frh, g2, fslot)];
                float y = tanhf(s1 + bs1[e]);
                int jg4 = (j0 + col) >> 2;
                out[((size_t)frow * TT + t) * HH + j0 + col] = y;
                h1w[((size_t)jg4 * BB + frow) * 4 + (col & 3)] = y;

                if (t < TT - 1) {
                    float s0 = 0.0f;
#pragma unroll
                    for (int g2 = 0; g2 < 8; ++g2) s0 += sred[RIDX(col + 8 * (2 + frh), g2, fslot)];
                    float pre = (e == 0) ? pn.x : pn.y;
                    ((float*)g_h0buf[(t + 1) & 1])[((size_t)jg4 * BB + frow) * 4 + (col & 3)] =
                        tanhf(s0 + pre + b0r[e]);
                } else {
                    float* hn = out + (size_t)BB * TT * HH;
                    hn[(size_t)(frow * 2 + 1) * HH + j0 + col] = y;
                    float l0 = __ldcg(&((const float*)g_h0buf[t & 1])[((size_t)jg4 * BB + frow) * 4 + (col & 3)]);
                    hn[(size_t)(frow * 2) * HH + j0 + col] = l0;
                }
            }
        }

        if (t < TT - 1) { grid_sync(ph * NBLK); ++ph; }
    }
}

/* ------------------------------------------------------------------ */
extern "C" void kernel_launch(void* const* d_in, const int* in_sizes, int n_in,
                              void* d_out, int out_size)
{
    const float* x  = (const float*)d_in[0];
    const float* h0 = (const float*)d_in[1];
    const float* Wi = (const float*)d_in[2];
    const float* bi = (const float*)d_in[3];
    const float* Wh = (const float*)d_in[4];
    const float* bh = (const float*)d_in[5];
    float* out = (float*)d_out;

    dim3 g2(16, 256);
    pre_gemm<<<g2, 256>>>(x, Wi, bi);

    size_t smem = 6144 * sizeof(float4) + (32 * 8 * 65 + 64) * sizeof(float);  /* ~161.5 KB */
    cudaFuncSetAttribute(rnn_persist, cudaFuncAttributeMaxDynamicSharedMemorySize, (int)smem);
    rnn_persist<<<NBLK, NTH, smem>>>(h0, Wi, bi, Wh, bh, out);
}